// round 9
// baseline (speedup 1.0000x reference)
#include <cuda_runtime.h>
#include <cuda_fp16.h>
#include <cstdint>

#define DD 64
#define KK 512
#define TILE_M 96
#define THREADS 384
#define PITCH 136          // halfs per row: [h1(64) | h2(64) | pad(8)]
#define PITCHB 272         // bytes per row (68 words ≡ 4 mod 32 -> ldmatrix conflict-free)

// smem layout (byte offsets)
#define SMB_B    0                       // 512 * 272 = 139264
#define SMB_A    139264                  // 96 * 272  = 26112
#define SMB_SC   165376                  // 512 floats = 2048
#define SMB_VAL  167424                  // float vals[96][4] = 1536
#define SMB_IDX  168960                  // int   idxs[96][4] = 1536
#define SMB_TOT  170496

__device__ __align__(16) __half g_B[KK * PITCH];
__device__ float g_sc[KK];

__device__ __forceinline__ uint32_t smem_u32(const void* p) {
    uint32_t a;
    asm("{ .reg .u64 t; cvta.to.shared.u64 t, %1; cvt.u32.u64 %0, t; }" : "=r"(a) : "l"(p));
    return a;
}

// split float4 -> fp16 hi (p1) and fp16 residual (p2)
__device__ __forceinline__ void pack_h12(float4 v, uint64_t& p1, uint64_t& p2) {
    __half a1 = __float2half_rn(v.x), b1 = __float2half_rn(v.y);
    __half c1 = __float2half_rn(v.z), d1 = __float2half_rn(v.w);
    __half a2 = __float2half_rn(v.x - __half2float(a1));
    __half b2 = __float2half_rn(v.y - __half2float(b1));
    __half c2 = __float2half_rn(v.z - __half2float(c1));
    __half d2 = __float2half_rn(v.w - __half2float(d1));
    p1 = (uint64_t)__half_as_ushort(a1) | ((uint64_t)__half_as_ushort(b1) << 16)
       | ((uint64_t)__half_as_ushort(c1) << 32) | ((uint64_t)__half_as_ushort(d1) << 48);
    p2 = (uint64_t)__half_as_ushort(a2) | ((uint64_t)__half_as_ushort(b2) << 16)
       | ((uint64_t)__half_as_ushort(c2) << 32) | ((uint64_t)__half_as_ushort(d2) << 48);
}

__device__ __forceinline__ void ldsm4(uint32_t* r, uint32_t addr) {
    asm volatile("ldmatrix.sync.aligned.m8n8.x4.shared.b16 {%0,%1,%2,%3}, [%4];"
                 : "=r"(r[0]), "=r"(r[1]), "=r"(r[2]), "=r"(r[3]) : "r"(addr));
}

__device__ __forceinline__ void mma16816(float* c, const uint32_t* a, uint32_t b0, uint32_t b1) {
    asm volatile("mma.sync.aligned.m16n8k16.row.col.f32.f16.f16.f32 "
                 "{%0,%1,%2,%3}, {%4,%5,%6,%7}, {%8,%9}, {%0,%1,%2,%3};"
                 : "+f"(c[0]), "+f"(c[1]), "+f"(c[2]), "+f"(c[3])
                 : "r"(a[0]), "r"(a[1]), "r"(a[2]), "r"(a[3]), "r"(b0), "r"(b1));
}

// ---- prep: split embedding rows into [Eh1 | Eh2] (pitch 136) + norms ----
__global__ void vq_prep(const float* __restrict__ emb) {
    int gid = blockIdx.x * blockDim.x + threadIdx.x;
    if (gid >= KK * 16) return;
    int k = gid >> 4, s = gid & 15;
    float4 v = ((const float4*)emb)[gid];
    uint64_t p1, p2;
    pack_h12(v, p1, p2);
    __half* row = g_B + k * PITCH;
    *(uint64_t*)(row + s * 4)      = p1;    // halfs  0..63 : Eh1
    *(uint64_t*)(row + 64 + s * 4) = p2;    // halfs 64..127: Eh2
    if (s == 0) {
        const float4* r = (const float4*)(emb + k * DD);
        float acc = 0.f;
        #pragma unroll
        for (int i = 0; i < 16; i++) {
            float4 e = r[i];
            acc += e.x * e.x + e.y * e.y + e.z * e.z + e.w * e.w;
        }
        g_sc[k] = 0.5f * acc;
    }
}

// ---- main: persistent HMMA GEMM + in-register argmin (12 warps, 3M x 4N) ----
__global__ __launch_bounds__(THREADS, 1)
void vq_hmma(const float* __restrict__ x,
             const float* __restrict__ emb,
             float* __restrict__ out,
             int N, int write_idx, int ntiles) {
    extern __shared__ char sm[];
    const uint32_t sb = smem_u32(sm);
    const int tid = threadIdx.x;
    const int wid = tid >> 5;
    const int lane = tid & 31;

    // Stage B + norms once per CTA
    {
        const uint4* s4 = (const uint4*)g_B;
        uint4* d4 = (uint4*)(sm + SMB_B);
        #pragma unroll 4
        for (int i = tid; i < KK * PITCHB / 16; i += THREADS) d4[i] = s4[i];
        for (int i = tid; i < KK; i += THREADS)
            ((float*)(sm + SMB_SC))[i] = g_sc[i];
    }

    const int mw = wid >> 2, nw = wid & 3;     // mw in 0..2, nw in 0..3
    const int m0 = mw * 32, n0 = nw * 128;
    uint32_t aaddr[2];
    #pragma unroll
    for (int sub = 0; sub < 2; sub++)
        aaddr[sub] = sb + SMB_A + (uint32_t)(m0 + sub * 16 + (lane & 15)) * PITCHB
                   + ((lane >> 4) & 1) * 16;
    const uint32_t baddr = sb + SMB_B
        + (uint32_t)(n0 + (lane & 7) + ((lane >> 4) & 1) * 8) * PITCHB
        + ((lane >> 3) & 1) * 16;

    // staging: each thread owns one quarter-row: row = tid>>2, segs q*4..q*4+3
    const int srow = tid >> 2;          // 0..95
    const int sq   = tid & 3;
    float* vals = (float*)(sm + SMB_VAL);
    int*   idxs = (int*)(sm + SMB_IDX);
    const float* scp = (const float*)(sm + SMB_SC);

    // Prefetch first tile (4 float4 per thread)
    float4 px[4];
    #pragma unroll
    for (int i = 0; i < 4; i++) px[i] = make_float4(0.f, 0.f, 0.f, 0.f);
    if (blockIdx.x < ntiles) {
        int g = blockIdx.x * TILE_M + srow;
        if (g < N) {
            #pragma unroll
            for (int i = 0; i < 4; i++)
                px[i] = ((const float4*)x)[(size_t)g * 16 + sq * 4 + i];
        }
    }

    for (int tile = blockIdx.x; tile < ntiles; tile += gridDim.x) {
        // ---- store A tile: [h1 | h2], pitch 272B ----
        {
            char* arow = sm + SMB_A + srow * PITCHB;
            #pragma unroll
            for (int i = 0; i < 4; i++) {
                uint64_t p1, p2;
                pack_h12(px[i], p1, p2);
                int s = sq * 4 + i;
                *(uint64_t*)(arow + s * 8)       = p1;  // h1
                *(uint64_t*)(arow + 128 + s * 8) = p2;  // h2
            }
        }
        // ---- prefetch next tile (overlaps GEMM) ----
        {
            int t2 = tile + gridDim.x;
            #pragma unroll
            for (int i = 0; i < 4; i++) px[i] = make_float4(0.f, 0.f, 0.f, 0.f);
            if (t2 < ntiles) {
                int g = t2 * TILE_M + srow;
                if (g < N) {
                    #pragma unroll
                    for (int i = 0; i < 4; i++)
                        px[i] = ((const float4*)x)[(size_t)g * 16 + sq * 4 + i];
                }
            }
        }
        __syncthreads();   // A visible (B visible since prologue)

        // ---- load A fragments once: 2 subtiles x 4 ksteps x (h1,h2) ----
        uint32_t ah1[2][4][4], ah2[2][4][4];
        #pragma unroll
        for (int sub = 0; sub < 2; sub++)
            #pragma unroll
            for (int s = 0; s < 4; s++) {
                ldsm4(ah1[sub][s], aaddr[sub] + s * 32);
                ldsm4(ah2[sub][s], aaddr[sub] + 128 + s * 32);
            }

        // running bests: [sub][rowA/rowB]
        float bv[2][2] = {{-3.402823466e38f, -3.402823466e38f},
                          {-3.402823466e38f, -3.402823466e38f}};
        int   bi[2][2] = {{0, 0}, {0, 0}};

        // ---- per n-pair (16 cols): load 8 B frags, 48 MMAs, argmin ----
        #pragma unroll 1
        for (int np = 0; np < 8; np++) {
            const uint32_t bb = baddr + np * (16 * PITCHB);
            uint32_t b1f[4][4], b2f[4][4];
            #pragma unroll
            for (int s = 0; s < 4; s++) ldsm4(b1f[s], bb + s * 32);        // Eh1
            #pragma unroll
            for (int s = 0; s < 4; s++) ldsm4(b2f[s], bb + 128 + s * 32);  // Eh2

            float c[2][2][4];
            #pragma unroll
            for (int sub = 0; sub < 2; sub++)
                #pragma unroll
                for (int t = 0; t < 2; t++)
                    c[sub][t][0] = c[sub][t][1] = c[sub][t][2] = c[sub][t][3] = 0.f;

            #pragma unroll
            for (int s = 0; s < 4; s++)
                #pragma unroll
                for (int sub = 0; sub < 2; sub++) {
                    mma16816(c[sub][0], ah1[sub][s], b1f[s][0], b1f[s][1]);  // h1.Eh1
                    mma16816(c[sub][1], ah1[sub][s], b1f[s][2], b1f[s][3]);
                }
            #pragma unroll
            for (int s = 0; s < 4; s++)
                #pragma unroll
                for (int sub = 0; sub < 2; sub++) {
                    mma16816(c[sub][0], ah1[sub][s], b2f[s][0], b2f[s][1]);  // h1.Eh2
                    mma16816(c[sub][1], ah1[sub][s], b2f[s][2], b2f[s][3]);
                }
            #pragma unroll
            for (int s = 0; s < 4; s++)
                #pragma unroll
                for (int sub = 0; sub < 2; sub++) {
                    mma16816(c[sub][0], ah2[sub][s], b1f[s][0], b1f[s][1]);  // h2.Eh1
                    mma16816(c[sub][1], ah2[sub][s], b1f[s][2], b1f[s][3]);
                }

            const int col0 = n0 + np * 16 + (lane & 3) * 2;
            const float s0 = scp[col0],     s1 = scp[col0 + 1];
            const float s2 = scp[col0 + 8], s3 = scp[col0 + 9];
            #pragma unroll
            for (int sub = 0; sub < 2; sub++) {
                float v;
                v = c[sub][0][0] - s0; if (v > bv[sub][0]) { bv[sub][0] = v; bi[sub][0] = col0; }
                v = c[sub][0][1] - s1; if (v > bv[sub][0]) { bv[sub][0] = v; bi[sub][0] = col0 + 1; }
                v = c[sub][1][0] - s2; if (v > bv[sub][0]) { bv[sub][0] = v; bi[sub][0] = col0 + 8; }
                v = c[sub][1][1] - s3; if (v > bv[sub][0]) { bv[sub][0] = v; bi[sub][0] = col0 + 9; }
                v = c[sub][0][2] - s0; if (v > bv[sub][1]) { bv[sub][1] = v; bi[sub][1] = col0; }
                v = c[sub][0][3] - s1; if (v > bv[sub][1]) { bv[sub][1] = v; bi[sub][1] = col0 + 1; }
                v = c[sub][1][2] - s2; if (v > bv[sub][1]) { bv[sub][1] = v; bi[sub][1] = col0 + 8; }
                v = c[sub][1][3] - s3; if (v > bv[sub][1]) { bv[sub][1] = v; bi[sub][1] = col0 + 9; }
            }
        }

        // ---- reduce across the 4 lanes sharing a row, write per-warp bests ----
        #pragma unroll
        for (int sub = 0; sub < 2; sub++)
            #pragma unroll
            for (int r = 0; r < 2; r++) {
                #pragma unroll
                for (int off = 1; off <= 2; off <<= 1) {
                    float ov = __shfl_xor_sync(0xffffffff, bv[sub][r], off);
                    int   oi = __shfl_xor_sync(0xffffffff, bi[sub][r], off);
                    if (ov > bv[sub][r] || (ov == bv[sub][r] && oi < bi[sub][r])) {
                        bv[sub][r] = ov; bi[sub][r] = oi;
                    }
                }
                if ((lane & 3) == 0) {
                    int row = m0 + sub * 16 + r * 8 + (lane >> 2);
                    vals[row * 4 + nw] = bv[sub][r];
                    idxs[row * 4 + nw] = bi[sub][r];
                }
            }
        __syncthreads();

        // ---- combine 4 N-warps per row ----
        if (tid < TILE_M) {
            float v = vals[tid * 4];  int b = idxs[tid * 4];
            #pragma unroll
            for (int w = 1; w < 4; w++) {
                float ov = vals[tid * 4 + w];  int oi = idxs[tid * 4 + w];
                if (ov > v || (ov == v && oi < b)) { v = ov; b = oi; }
            }
            idxs[tid * 4] = b;
            if (write_idx) {
                int g = tile * TILE_M + tid;
                if (g < N) out[(size_t)N * DD + g] = (float)b;
            }
        }
        __syncthreads();

        // ---- gather output rows from embedding (L2-resident) ----
        {
            int g = tile * TILE_M + srow;
            if (g < N) {
                int idx = idxs[srow * 4];
                #pragma unroll
                for (int i = 0; i < 4; i++) {
                    int seg = sq * 4 + i;
                    ((float4*)out)[(size_t)g * 16 + seg] =
                        ((const float4*)emb)[(size_t)idx * 16 + seg];
                }
            }
        }
    }
}

extern "C" void kernel_launch(void* const* d_in, const int* in_sizes, int n_in,
                              void* d_out, int out_size) {
    const float* x   = (const float*)d_in[0];   // flat_x  [N, 64]
    const float* emb = (const float*)d_in[1];   // codes   [512, 64]
    float* out = (float*)d_out;

    const int N = in_sizes[0] / DD;
    const int write_idx = (out_size >= N * DD + N) ? 1 : 0;
    const int ntiles = (N + TILE_M - 1) / TILE_M;

    vq_prep<<<32, 256>>>(emb);

    cudaFuncSetAttribute(vq_hmma,
                         cudaFuncAttributeMaxDynamicSharedMemorySize, SMB_TOT);
    vq_hmma<<<148, THREADS, SMB_TOT>>>(x, emb, out, N, write_idx, ntiles);
}

// round 12
// speedup vs baseline: 1.1562x; 1.1562x over previous
#include <cuda_runtime.h>
#include <cuda_fp16.h>
#include <cstdint>

#define DD 64
#define KK 512
#define TILE_M 64
#define THREADS 256
#define PITCH 136          // halfs per row: [h1(64) | h2(64) | pad(8)]
#define PITCHB 272         // bytes per row (68 words ≡ 4 mod 32 -> ldmatrix conflict-free)

// smem layout (byte offsets)
#define SMB_B    0                       // 512 * 272 = 139264
#define SMB_A    139264                  // 64 * 272  = 17408
#define SMB_SC   156672                  // 512 floats = 2048
#define SMB_VAL  158720                  // float vals[64][4] = 1024
#define SMB_IDX  159744                  // int   idxs[64][4] = 1024
#define SMB_TOT  160768

__device__ __align__(16) __half g_B[KK * PITCH];
__device__ float g_sc[KK];

__device__ __forceinline__ uint32_t smem_u32(const void* p) {
    uint32_t a;
    asm("{ .reg .u64 t; cvta.to.shared.u64 t, %1; cvt.u32.u64 %0, t; }" : "=r"(a) : "l"(p));
    return a;
}

// split float4 -> fp16 hi (p1) and fp16 residual (p2)
__device__ __forceinline__ void pack_h12(float4 v, uint64_t& p1, uint64_t& p2) {
    __half a1 = __float2half_rn(v.x), b1 = __float2half_rn(v.y);
    __half c1 = __float2half_rn(v.z), d1 = __float2half_rn(v.w);
    __half a2 = __float2half_rn(v.x - __half2float(a1));
    __half b2 = __float2half_rn(v.y - __half2float(b1));
    __half c2 = __float2half_rn(v.z - __half2float(c1));
    __half d2 = __float2half_rn(v.w - __half2float(d1));
    p1 = (uint64_t)__half_as_ushort(a1) | ((uint64_t)__half_as_ushort(b1) << 16)
       | ((uint64_t)__half_as_ushort(c1) << 32) | ((uint64_t)__half_as_ushort(d1) << 48);
    p2 = (uint64_t)__half_as_ushort(a2) | ((uint64_t)__half_as_ushort(b2) << 16)
       | ((uint64_t)__half_as_ushort(c2) << 32) | ((uint64_t)__half_as_ushort(d2) << 48);
}

__device__ __forceinline__ void ldsm4(uint32_t* r, uint32_t addr) {
    asm volatile("ldmatrix.sync.aligned.m8n8.x4.shared.b16 {%0,%1,%2,%3}, [%4];"
                 : "=r"(r[0]), "=r"(r[1]), "=r"(r[2]), "=r"(r[3]) : "r"(addr));
}

__device__ __forceinline__ void mma16816(float* c, const uint32_t* a, uint32_t b0, uint32_t b1) {
    asm volatile("mma.sync.aligned.m16n8k16.row.col.f32.f16.f16.f32 "
                 "{%0,%1,%2,%3}, {%4,%5,%6,%7}, {%8,%9}, {%0,%1,%2,%3};"
                 : "+f"(c[0]), "+f"(c[1]), "+f"(c[2]), "+f"(c[3])
                 : "r"(a[0]), "r"(a[1]), "r"(a[2]), "r"(a[3]), "r"(b0), "r"(b1));
}

// ---- prep: split embedding rows into [Eh1 | Eh2] (pitch 136) + norms ----
__global__ void vq_prep(const float* __restrict__ emb) {
    int gid = blockIdx.x * blockDim.x + threadIdx.x;
    if (gid >= KK * 16) return;
    int k = gid >> 4, s = gid & 15;
    float4 v = ((const float4*)emb)[gid];
    uint64_t p1, p2;
    pack_h12(v, p1, p2);
    __half* row = g_B + k * PITCH;
    *(uint64_t*)(row + s * 4)      = p1;    // halfs  0..63 : Eh1
    *(uint64_t*)(row + 64 + s * 4) = p2;    // halfs 64..127: Eh2
    if (s == 0) {
        const float4* r = (const float4*)(emb + k * DD);
        float acc = 0.f;
        #pragma unroll
        for (int i = 0; i < 16; i++) {
            float4 e = r[i];
            acc += e.x * e.x + e.y * e.y + e.z * e.z + e.w * e.w;
        }
        g_sc[k] = 0.5f * acc;
    }
}

// Compute the 48 MMAs for one n-pair into c[2][2][4]
__device__ __forceinline__ void do_np_mmas(float c[2][2][4],
                                           const uint32_t ah1[2][4][4],
                                           const uint32_t ah2[2][4][4],
                                           const uint32_t b1f[4][4],
                                           const uint32_t b2f[4][4]) {
    #pragma unroll
    for (int sub = 0; sub < 2; sub++)
        #pragma unroll
        for (int t = 0; t < 2; t++)
            c[sub][t][0] = c[sub][t][1] = c[sub][t][2] = c[sub][t][3] = 0.f;
    #pragma unroll
    for (int s = 0; s < 4; s++)
        #pragma unroll
        for (int sub = 0; sub < 2; sub++) {
            mma16816(c[sub][0], ah1[sub][s], b1f[s][0], b1f[s][1]);  // h1.Eh1
            mma16816(c[sub][1], ah1[sub][s], b1f[s][2], b1f[s][3]);
        }
    #pragma unroll
    for (int s = 0; s < 4; s++)
        #pragma unroll
        for (int sub = 0; sub < 2; sub++) {
            mma16816(c[sub][0], ah1[sub][s], b2f[s][0], b2f[s][1]);  // h1.Eh2
            mma16816(c[sub][1], ah1[sub][s], b2f[s][2], b2f[s][3]);
        }
    #pragma unroll
    for (int s = 0; s < 4; s++)
        #pragma unroll
        for (int sub = 0; sub < 2; sub++) {
            mma16816(c[sub][0], ah2[sub][s], b1f[s][0], b1f[s][1]);  // h2.Eh1
            mma16816(c[sub][1], ah2[sub][s], b1f[s][2], b1f[s][3]);
        }
}

// Argmin update for one n-pair's results (ascending col order, strict >)
__device__ __forceinline__ void do_np_cmp(const float c[2][2][4],
                                          float bv[2][2], int bi[2][2],
                                          const float* scp, int col0) {
    const float s0 = scp[col0],     s1 = scp[col0 + 1];
    const float s2 = scp[col0 + 8], s3 = scp[col0 + 9];
    #pragma unroll
    for (int sub = 0; sub < 2; sub++) {
        float v;
        v = c[sub][0][0] - s0; if (v > bv[sub][0]) { bv[sub][0] = v; bi[sub][0] = col0; }
        v = c[sub][0][1] - s1; if (v > bv[sub][0]) { bv[sub][0] = v; bi[sub][0] = col0 + 1; }
        v = c[sub][1][0] - s2; if (v > bv[sub][0]) { bv[sub][0] = v; bi[sub][0] = col0 + 8; }
        v = c[sub][1][1] - s3; if (v > bv[sub][0]) { bv[sub][0] = v; bi[sub][0] = col0 + 9; }
        v = c[sub][0][2] - s0; if (v > bv[sub][1]) { bv[sub][1] = v; bi[sub][1] = col0; }
        v = c[sub][0][3] - s1; if (v > bv[sub][1]) { bv[sub][1] = v; bi[sub][1] = col0 + 1; }
        v = c[sub][1][2] - s2; if (v > bv[sub][1]) { bv[sub][1] = v; bi[sub][1] = col0 + 8; }
        v = c[sub][1][3] - s3; if (v > bv[sub][1]) { bv[sub][1] = v; bi[sub][1] = col0 + 9; }
    }
}

// ---- main: persistent HMMA GEMM + in-register argmin (8 warps, 2M x 4N) ----
__global__ __launch_bounds__(THREADS, 1)
void vq_hmma(const float* __restrict__ x,
             const float* __restrict__ emb,
             float* __restrict__ out,
             int N, int write_idx, int ntiles) {
    extern __shared__ char sm[];
    const uint32_t sb = smem_u32(sm);
    const int tid = threadIdx.x;
    const int wid = tid >> 5;
    const int lane = tid & 31;

    // Stage B + norms once per CTA
    {
        const uint4* s4 = (const uint4*)g_B;
        uint4* d4 = (uint4*)(sm + SMB_B);
        #pragma unroll 4
        for (int i = tid; i < KK * PITCHB / 16; i += THREADS) d4[i] = s4[i];
        for (int i = tid; i < KK; i += THREADS)
            ((float*)(sm + SMB_SC))[i] = g_sc[i];
    }

    const int mw = wid >> 2, nw = wid & 3;
    const int m0 = mw * 32, n0 = nw * 128;
    uint32_t aaddr[2];
    #pragma unroll
    for (int sub = 0; sub < 2; sub++)
        aaddr[sub] = sb + SMB_A + (uint32_t)(m0 + sub * 16 + (lane & 15)) * PITCHB
                   + ((lane >> 4) & 1) * 16;
    const uint32_t baddr = sb + SMB_B
        + (uint32_t)(n0 + (lane & 7) + ((lane >> 4) & 1) * 8) * PITCHB
        + ((lane >> 3) & 1) * 16;

    const int srow = tid >> 3;          // staging row base (0..31), +32 for j=1
    const int sseg = tid & 7;           // float4-pair segment
    float* vals = (float*)(sm + SMB_VAL);
    int*   idxs = (int*)(sm + SMB_IDX);
    const float* scp = (const float*)(sm + SMB_SC);

    // Prefetch first tile
    float4 pa[2], pb[2];
    #pragma unroll
    for (int j = 0; j < 2; j++) { pa[j] = make_float4(0,0,0,0); pb[j] = pa[j]; }
    if (blockIdx.x < ntiles) {
        #pragma unroll
        for (int j = 0; j < 2; j++) {
            int g = blockIdx.x * TILE_M + srow + j * 32;
            if (g < N) {
                pa[j] = ((const float4*)x)[(size_t)g * 16 + sseg * 2];
                pb[j] = ((const float4*)x)[(size_t)g * 16 + sseg * 2 + 1];
            }
        }
    }

    for (int tile = blockIdx.x; tile < ntiles; tile += gridDim.x) {
        // ---- store A tile: [h1 | h2], pitch 272B ----
        #pragma unroll
        for (int j = 0; j < 2; j++) {
            uint64_t a1, a2, b1, b2;
            pack_h12(pa[j], a1, a2);
            pack_h12(pb[j], b1, b2);
            char* arow = sm + SMB_A + (srow + j * 32) * PITCHB + sseg * 16;
            *(uint64_t*)(arow)       = a1;  *(uint64_t*)(arow + 8)   = b1;  // h1
            *(uint64_t*)(arow + 128) = a2;  *(uint64_t*)(arow + 136) = b2;  // h2
        }
        // ---- prefetch next tile (overlaps GEMM) ----
        {
            int t2 = tile + gridDim.x;
            #pragma unroll
            for (int j = 0; j < 2; j++) { pa[j] = make_float4(0,0,0,0); pb[j] = pa[j]; }
            if (t2 < ntiles) {
                #pragma unroll
                for (int j = 0; j < 2; j++) {
                    int g = t2 * TILE_M + srow + j * 32;
                    if (g < N) {
                        pa[j] = ((const float4*)x)[(size_t)g * 16 + sseg * 2];
                        pb[j] = ((const float4*)x)[(size_t)g * 16 + sseg * 2 + 1];
                    }
                }
            }
        }
        __syncthreads();   // A visible (B visible since prologue)

        // ---- load A fragments once: 2 subtiles x 4 ksteps x (h1,h2) ----
        uint32_t ah1[2][4][4], ah2[2][4][4];
        #pragma unroll
        for (int sub = 0; sub < 2; sub++)
            #pragma unroll
            for (int s = 0; s < 4; s++) {
                ldsm4(ah1[sub][s], aaddr[sub] + s * 32);
                ldsm4(ah2[sub][s], aaddr[sub] + 128 + s * 32);
            }

        // running bests: [sub][rowA/rowB]
        float bv[2][2] = {{-3.402823466e38f, -3.402823466e38f},
                          {-3.402823466e38f, -3.402823466e38f}};
        int   bi[2][2] = {{0, 0}, {0, 0}};

        // ---- software-pipelined n-pairs: two at a time ----
        // np0's compare chain overlaps np1's MMA stream (independent regs).
        #pragma unroll 1
        for (int npp = 0; npp < 4; npp++) {
            const int np0 = npp * 2, np1 = npp * 2 + 1;
            const uint32_t bb0 = baddr + np0 * (16 * PITCHB);
            const uint32_t bb1 = baddr + np1 * (16 * PITCHB);

            uint32_t b1f0[4][4], b2f0[4][4], b1f1[4][4], b2f1[4][4];
            #pragma unroll
            for (int s = 0; s < 4; s++) ldsm4(b1f0[s], bb0 + s * 32);
            #pragma unroll
            for (int s = 0; s < 4; s++) ldsm4(b2f0[s], bb0 + 128 + s * 32);
            #pragma unroll
            for (int s = 0; s < 4; s++) ldsm4(b1f1[s], bb1 + s * 32);
            #pragma unroll
            for (int s = 0; s < 4; s++) ldsm4(b2f1[s], bb1 + 128 + s * 32);

            float c0[2][2][4], c1[2][2][4];
            do_np_mmas(c0, ah1, ah2, b1f0, b2f0);
            do_np_mmas(c1, ah1, ah2, b1f1, b2f1);   // independent of c0's compares

            do_np_cmp(c0, bv, bi, scp, n0 + np0 * 16 + (lane & 3) * 2);
            do_np_cmp(c1, bv, bi, scp, n0 + np1 * 16 + (lane & 3) * 2);
        }

        // ---- reduce across the 4 lanes sharing a row, write per-warp bests ----
        #pragma unroll
        for (int sub = 0; sub < 2; sub++)
            #pragma unroll
            for (int r = 0; r < 2; r++) {
                #pragma unroll
                for (int off = 1; off <= 2; off <<= 1) {
                    float ov = __shfl_xor_sync(0xffffffff, bv[sub][r], off);
                    int   oi = __shfl_xor_sync(0xffffffff, bi[sub][r], off);
                    if (ov > bv[sub][r] || (ov == bv[sub][r] && oi < bi[sub][r])) {
                        bv[sub][r] = ov; bi[sub][r] = oi;
                    }
                }
                if ((lane & 3) == 0) {
                    int row = m0 + sub * 16 + r * 8 + (lane >> 2);
                    vals[row * 4 + nw] = bv[sub][r];
                    idxs[row * 4 + nw] = bi[sub][r];
                }
            }
        __syncthreads();

        // ---- combine 4 N-warps per row ----
        if (tid < TILE_M) {
            float v = vals[tid * 4];  int b = idxs[tid * 4];
            #pragma unroll
            for (int w = 1; w < 4; w++) {
                float ov = vals[tid * 4 + w];  int oi = idxs[tid * 4 + w];
                if (ov > v || (ov == v && oi < b)) { v = ov; b = oi; }
            }
            idxs[tid * 4] = b;
            if (write_idx) {
                int g = tile * TILE_M + tid;
                if (g < N) out[(size_t)N * DD + g] = (float)b;
            }
        }
        __syncthreads();

        // ---- gather output rows from embedding (L2-resident) ----
        {
            int row = tid >> 2;
            int g = tile * TILE_M + row;
            if (g < N) {
                int idx = idxs[row * 4];
                #pragma unroll
                for (int j = 0; j < 4; j++) {
                    int seg = (tid & 3) + j * 4;
                    ((float4*)out)[(size_t)g * 16 + seg] =
                        ((const float4*)emb)[(size_t)idx * 16 + seg];
                }
            }
        }
    }
}

extern "C" void kernel_launch(void* const* d_in, const int* in_sizes, int n_in,
                              void* d_out, int out_size) {
    const float* x   = (const float*)d_in[0];   // flat_x  [N, 64]
    const float* emb = (const float*)d_in[1];   // codes   [512, 64]
    float* out = (float*)d_out;

    const int N = in_sizes[0] / DD;
    const int write_idx = (out_size >= N * DD + N) ? 1 : 0;
    const int ntiles = (N + TILE_M - 1) / TILE_M;

    vq_prep<<<32, 256>>>(emb);

    cudaFuncSetAttribute(vq_hmma,
                         cudaFuncAttributeMaxDynamicSharedMemorySize, SMB_TOT);
    vq_hmma<<<148, THREADS, SMB_TOT>>>(x, emb, out, N, write_idx, ntiles);
}